// round 8
// baseline (speedup 1.0000x reference)
#include <cuda_runtime.h>
#include <cuda_bf16.h>
#include <cstdint>
#include <cstddef>

// RNN-T beam search. B=8, T=128, H=1024, V=4096, K=5 (M = 40 hyps).
// Persistent kernel, 3 CTAs/SM (444 CTAs), cp.async double-buffered split-K
// GEMMs (tile 40x128), packed fma.rn.f32x2 inner loops.

#define HH   1024
#define VV   4096
#define BB   8
#define KBM  5
#define MM   40
#define TT   128
#define GRID_ALL 444
#define NSPL 13           // k-splits for gates/out
#define NEGF -3.0e38f

typedef unsigned long long u64;

// ----------------------------- device state --------------------------------
__device__ __align__(16) float g_tnproj[BB * TT * HH];     // 4 MB
__device__ __align__(16) float g_WcatT[2048 * 4096];       // 32 MB [k][n'] gate-permuted
__device__ __align__(16) float g_blstm_p[4096];            // permuted bias [4u+g]
__device__ __align__(16) float g_bufA[16 * MM * VV];       // gates/out partials (NSPL slices)
__device__ __align__(16) float g_bufB[32 * MM * HH];       // pn partials
__device__ __align__(16) float g_h[2][MM * HH];
__device__ __align__(16) float g_c[2][MM * HH];
__device__ __align__(16) float g_hnew[MM * HH];
__device__ __align__(16) float g_cnew[MM * HH];
__device__ __align__(16) float g_joint[MM * HH];
__device__ float g_rmax[MM * 128];
__device__ float g_rsum[MM * 128];
__device__ float g_t5v[MM * 640];
__device__ int   g_t5i[MM * 640];
__device__ float g_scores[2][MM];
__device__ int   g_tokens[2][MM];
__device__ int   g_lens[2][MM];
__device__ int   g_preds[2][MM * TT];
__device__ unsigned int g_barcnt;

__device__ __forceinline__ float sigm(float x) { return 1.0f / (1.0f + expf(-x)); }

// ----------------------------- packed f32x2 ---------------------------------
__device__ __forceinline__ u64 pk2(float a) {
    u64 r;
    asm("mov.b64 %0, {%1, %1};" : "=l"(r) : "f"(a));
    return r;
}
__device__ __forceinline__ void fma2(u64& d, u64 a, u64 b) {
    asm("fma.rn.f32x2 %0, %1, %2, %0;" : "+l"(d) : "l"(a), "l"(b));
}

// ----------------------------- cp.async helpers -----------------------------
__device__ __forceinline__ void cpa16(void* s, const void* g) {
    uint32_t sa = (uint32_t)__cvta_generic_to_shared(s);
    asm volatile("cp.async.cg.shared.global [%0], [%1], 16;" :: "r"(sa), "l"(g));
}
#define CPA_COMMIT()  asm volatile("cp.async.commit_group;" ::: "memory")
#define CPA_WAIT(N)   asm volatile("cp.async.wait_group %0;" :: "n"(N) : "memory")

// ---------------------- grid barrier (monotonic counter) --------------------
__device__ __forceinline__ void gbar(unsigned int& ph) {
    __syncthreads();
    ph++;
    if (threadIdx.x == 0) {
        __threadfence();
        atomicAdd(&g_barcnt, 1u);
        unsigned int target = ph * (unsigned int)GRID_ALL;
        while (*(volatile unsigned int*)&g_barcnt < target) __nanosleep(32);
        __threadfence();
    }
    __syncthreads();
}

// ----------------------------- init ----------------------------------------
__global__ void init_state(const float* __restrict__ b_lstm) {
    int idx = blockIdx.x * 256 + threadIdx.x;   // 160*256 = 40960
    if (idx < MM * HH) { g_h[0][idx] = 0.0f; g_c[0][idx] = 0.0f; }
    if (idx < MM) {
        g_scores[0][idx] = (idx % KBM == 0) ? 0.0f : -1e9f;
        g_tokens[0][idx] = 0;
        g_lens[0][idx]   = 0;
    }
    if (idx < MM * TT) g_preds[0][idx] = 0;
    if (idx < 4096) g_blstm_p[idx] = b_lstm[(idx & 3) * 1024 + (idx >> 2)];
    if (idx == 0) g_barcnt = 0u;
}

// --------------------- weight transpose + gate permute ----------------------
__global__ void permute_w(const float* __restrict__ Wih,
                          const float* __restrict__ Whh) {
    __shared__ float tile[32][33];
    int x = threadIdx.x, y0 = threadIdx.y;
    int kt = blockIdx.x * 32, nt = blockIdx.y * 32;
#pragma unroll
    for (int yy = 0; yy < 32; yy += 8) {
        int np = nt + y0 + yy;
        int row = (np & 3) * 1024 + (np >> 2);
        int k = kt + x;
        float v = (k < 1024) ? Wih[(size_t)row * 1024 + k]
                             : Whh[(size_t)row * 1024 + k - 1024];
        tile[y0 + yy][x] = v;
    }
    __syncthreads();
#pragma unroll
    for (int yy = 0; yy < 32; yy += 8) {
        int k = kt + y0 + yy;
        int np = nt + x;
        g_WcatT[(size_t)k * 4096 + np] = tile[x][y0 + yy];
    }
}

// ----------------------------- tn_proj GEMM --------------------------------
__global__ __launch_bounds__(256) void tnproj_gemm(const float* __restrict__ A,
                                                   const float* __restrict__ Bm) {
    __shared__ float As[16][65];
    __shared__ float Bs[16][64];
    int tid = threadIdx.x;
    int tx = tid & 15, ty = tid >> 4;
    int m0 = blockIdx.y * 64, n0 = blockIdx.x * 64;
    float acc[4][4];
#pragma unroll
    for (int i = 0; i < 4; i++)
#pragma unroll
        for (int j = 0; j < 4; j++) acc[i][j] = 0.0f;
    for (int kk = 0; kk < 1024; kk += 16) {
        {
            int mm = tid >> 2;
            int kq = (tid & 3) * 4;
            float4 v = *(const float4*)&A[(size_t)(m0 + mm) * 1024 + kk + kq];
            As[kq + 0][mm] = v.x; As[kq + 1][mm] = v.y;
            As[kq + 2][mm] = v.z; As[kq + 3][mm] = v.w;
        }
#pragma unroll
        for (int r = 0; r < 4; r++) {
            int idx = tid + r * 256;
            int k = idx >> 6, n = idx & 63;
            Bs[k][n] = Bm[(size_t)(kk + k) * 1024 + n0 + n];
        }
        __syncthreads();
#pragma unroll
        for (int k = 0; k < 16; k++) {
            float a[4], b[4];
#pragma unroll
            for (int i = 0; i < 4; i++) a[i] = As[k][ty + 16 * i];
#pragma unroll
            for (int j = 0; j < 4; j++) b[j] = Bs[k][tx + 16 * j];
#pragma unroll
            for (int i = 0; i < 4; i++)
#pragma unroll
                for (int j = 0; j < 4; j++) acc[i][j] += a[i] * b[j];
        }
        __syncthreads();
    }
#pragma unroll
    for (int i = 0; i < 4; i++)
#pragma unroll
        for (int j = 0; j < 4; j++)
            g_tnproj[(size_t)(m0 + ty + 16 * i) * 1024 + n0 + tx + 16 * j] = acc[i][j];
}

// =========================== persistent stages ==============================
struct Smem {
    float As[2][MM][32];      // gates/out A tiles; pn uses As[0] as [20][32]
    float Bs[2][32][128];     // gates/out B; pn views whole region as [32][256]
    int   tok[MM];
};

// FFMA2 inner product, tile 40x128: thread owns col pairs {nn2, nn2+1} and
// {nn2+64, nn2+65}; rows mg*5..mg*5+4.
__device__ __forceinline__ void mmc128(const float (*As)[32], const float (*Bs)[128],
                                       u64 acc[5][2], int nn2, int mg) {
#pragma unroll 4
    for (int kk = 0; kk < 32; kk++) {
        u64 b0 = *(const u64*)&Bs[kk][nn2];
        u64 b1 = *(const u64*)&Bs[kk][nn2 + 64];
#pragma unroll
        for (int i = 0; i < 5; i++) {
            u64 a2 = pk2(As[mg * 5 + i][kk]);
            fma2(acc[i][0], a2, b0);
            fma2(acc[i][1], a2, b1);
        }
    }
}

// gates: 32 col-blocks(128) x 13 k-splits = 416 CTAs. 64 chunks distributed
// 4/5 per split. Slices indexed by ks.
__device__ void gates_stage(Smem* sm, int blk, int cur, const float* __restrict__ E) {
    int tid = threadIdx.x;
    int cb = blk & 31, ks = blk >> 5;      // blk < 416
    int n0 = cb * 128;
    int c0 = (64 * ks) / NSPL, c1 = (64 * (ks + 1)) / NSPL;
    if (tid < MM) sm->tok[tid] = g_tokens[cur][tid];
    __syncthreads();

    auto stage = [&](int c) {
        int kg = c * 32;
        int buf = c & 1;
#pragma unroll
        for (int r = 0; r < 2; r++) {
            int idx = tid + r * 256;
            if (idx < 320) {
                int m = idx >> 3, q = (idx & 7) * 4;
                const float* src = (kg < 1024)
                    ? &E[(size_t)sm->tok[m] * HH + kg + q]
                    : &g_h[cur][m * HH + (kg - 1024) + q];
                cpa16(&sm->As[buf][m][q], src);
            }
        }
#pragma unroll
        for (int r = 0; r < 4; r++) {
            int idx = tid + r * 256;
            int kk = idx >> 5, nq = (idx & 31) * 4;
            cpa16(&sm->Bs[buf][kk][nq], &g_WcatT[(size_t)(kg + kk) * 4096 + n0 + nq]);
        }
        CPA_COMMIT();
    };

    u64 acc[5][2];
#pragma unroll
    for (int i = 0; i < 5; i++) { acc[i][0] = 0ull; acc[i][1] = 0ull; }
    int nn2 = (tid & 31) * 2, mg = tid >> 5;

    stage(c0);
    for (int c = c0; c < c1; c++) {
        if (c + 1 < c1) { stage(c + 1); CPA_WAIT(1); }
        else            { CPA_WAIT(0); }
        __syncthreads();
        mmc128(sm->As[c & 1], sm->Bs[c & 1], acc, nn2, mg);
        __syncthreads();
    }
    float* p = g_bufA + (size_t)ks * MM * VV;
#pragma unroll
    for (int i = 0; i < 5; i++) {
        *(u64*)&p[(mg * 5 + i) * VV + n0 + nn2]      = acc[i][0];
        *(u64*)&p[(mg * 5 + i) * VV + n0 + 64 + nn2] = acc[i][1];
    }
}

// pn: 2 m-halves x 4 col-blocks(256) x 32 k-splits(32) = 256 CTAs.
// Tile 20x256. LSTM-reduce prologue over NSPL gates slices.
__device__ void pn_stage(Smem* sm, int blk, int cur, const float* __restrict__ Wpn) {
    int tid = threadIdx.x;
    int mh = blk & 1;
    int cb = (blk >> 1) & 3;
    int s  = blk >> 3;                 // 0..31
    int n0 = cb * 256, kl = s * 32, mb = mh * 20;
    float* Bs1 = &sm->Bs[0][0][0];     // view as [32][256]
    float (*As)[32] = sm->As[0];       // rows 0..19 used

#pragma unroll
    for (int r = 0; r < 8; r++) {
        int idx = tid + r * 256;
        int kk = idx >> 6, nq = (idx & 63) * 4;
        cpa16(&Bs1[kk * 256 + nq], &Wpn[(size_t)(kl + kk) * HH + n0 + nq]);
    }
    CPA_COMMIT();

    // LSTM prologue: hnew for rows mb..mb+19, units kl..kl+31
#pragma unroll
    for (int r = 0; r < 3; r++) {
        int idx = tid + r * 256;
        if (idx < 640) {
            int ml = idx >> 5, kk = idx & 31;
            int m = mb + ml, u = kl + kk;
            float4 s4 = make_float4(0.f, 0.f, 0.f, 0.f);
#pragma unroll
            for (int sp = 0; sp < NSPL; sp++) {
                float4 q = *(const float4*)&g_bufA[(size_t)sp * MM * VV + m * VV + 4 * u];
                s4.x += q.x; s4.y += q.y; s4.z += q.z; s4.w += q.w;
            }
            float4 bb = *(const float4*)&g_blstm_p[4 * u];
            float gi = s4.x + bb.x, gf = s4.y + bb.y, gg = s4.z + bb.z, go = s4.w + bb.w;
            float co = g_c[cur][m * HH + u];
            float cn = sigm(gf) * co + sigm(gi) * tanhf(gg);
            float hn = sigm(go) * tanhf(cn);
            As[ml][kk] = hn;
            if (cb == 0) { g_hnew[m * HH + u] = hn; g_cnew[m * HH + u] = cn; }
        }
    }
    CPA_WAIT(0);
    __syncthreads();

    u64 acc[5][2];
#pragma unroll
    for (int i = 0; i < 5; i++) { acc[i][0] = 0ull; acc[i][1] = 0ull; }
    int nn2 = (tid & 63) * 2, mg = tid >> 6;    // mg 0..3
#pragma unroll 4
    for (int kk = 0; kk < 32; kk++) {
        u64 b0 = *(const u64*)&Bs1[kk * 256 + nn2];
        u64 b1 = *(const u64*)&Bs1[kk * 256 + nn2 + 128];
#pragma unroll
        for (int i = 0; i < 5; i++) {
            u64 a2 = pk2(As[mg * 5 + i][kk]);
            fma2(acc[i][0], a2, b0);
            fma2(acc[i][1], a2, b1);
        }
    }
    float* p = g_bufB + (size_t)s * MM * HH;
#pragma unroll
    for (int i = 0; i < 5; i++) {
        int row = mb + mg * 5 + i;
        *(u64*)&p[row * HH + n0 + nn2]       = acc[i][0];
        *(u64*)&p[row * HH + n0 + 128 + nn2] = acc[i][1];
    }
}

// joint: all CTAs, reduce 32 pn partials + bias + tnproj -> tanh
__device__ void joint_stage(const float* __restrict__ b_joint, int t, int blk) {
    for (int e = blk * 256 + threadIdx.x; e < MM * HH; e += GRID_ALL * 256) {
        int m = e >> 10, j = e & 1023;
        float v = b_joint[j];
#pragma unroll
        for (int s = 0; s < 32; s++) v += g_bufB[(size_t)s * MM * HH + e];
        int b = m / KBM;
        v += g_tnproj[((size_t)b * TT + t) * HH + j];
        g_joint[e] = tanhf(v);
    }
}

// out: 32 col-blocks(128) x 13 k-splits = 416 CTAs. 32 chunks distributed 2/3.
__device__ void out_stage(Smem* sm, int blk, const float* __restrict__ Wout) {
    int tid = threadIdx.x;
    int cb = blk & 31, ks = blk >> 5;
    int n0 = cb * 128;
    int c0 = (32 * ks) / NSPL, c1 = (32 * (ks + 1)) / NSPL;

    auto stage = [&](int c) {
        int kg = c * 32;
        int buf = c & 1;
#pragma unroll
        for (int r = 0; r < 2; r++) {
            int idx = tid + r * 256;
            if (idx < 320) {
                int m = idx >> 3, q = (idx & 7) * 4;
                cpa16(&sm->As[buf][m][q], &g_joint[m * HH + kg + q]);
            }
        }
#pragma unroll
        for (int r = 0; r < 4; r++) {
            int idx = tid + r * 256;
            int kk = idx >> 5, nq = (idx & 31) * 4;
            cpa16(&sm->Bs[buf][kk][nq], &Wout[(size_t)(kg + kk) * VV + n0 + nq]);
        }
        CPA_COMMIT();
    };

    u64 acc[5][2];
#pragma unroll
    for (int i = 0; i < 5; i++) { acc[i][0] = 0ull; acc[i][1] = 0ull; }
    int nn2 = (tid & 31) * 2, mg = tid >> 5;

    stage(c0);
    for (int c = c0; c < c1; c++) {
        if (c + 1 < c1) { stage(c + 1); CPA_WAIT(1); }
        else            { CPA_WAIT(0); }
        __syncthreads();
        mmc128(sm->As[c & 1], sm->Bs[c & 1], acc, nn2, mg);
        __syncthreads();
    }
    float* p = g_bufA + (size_t)ks * MM * VV;
#pragma unroll
    for (int i = 0; i < 5; i++) {
        *(u64*)&p[(mg * 5 + i) * VV + n0 + nn2]      = acc[i][0];
        *(u64*)&p[(mg * 5 + i) * VV + n0 + 64 + nn2] = acc[i][1];
    }
}

// stats: all CTAs. 5120 (row, 32-col slice) tasks; reduce NSPL out partials.
__device__ void stats_stage(int blk, const float* __restrict__ bout) {
    int warp = threadIdx.x >> 5, lane = threadIdx.x & 31;
    unsigned full = 0xffffffffu;
    for (int tk = blk * 8 + warp; tk < MM * 128; tk += GRID_ALL * 8) {
        int row = tk >> 7, sl = tk & 127;
        int col = sl * 32 + lane;
        float v = bout[col];
#pragma unroll
        for (int sp = 0; sp < NSPL; sp++)
            v += g_bufA[(size_t)sp * MM * VV + (size_t)row * VV + col];
        float mx = v;
#pragma unroll
        for (int off = 16; off > 0; off >>= 1)
            mx = fmaxf(mx, __shfl_xor_sync(full, mx, off));
        float se = expf(v - mx);
#pragma unroll
        for (int off = 16; off > 0; off >>= 1)
            se += __shfl_xor_sync(full, se, off);
        bool chosen = false;
        for (int j = 0; j < KBM; j++) {
            float cv = chosen ? NEGF : v;
            int ci = col;
#pragma unroll
            for (int off = 16; off > 0; off >>= 1) {
                float ov = __shfl_xor_sync(full, cv, off);
                int   oi = __shfl_xor_sync(full, ci, off);
                if (ov > cv || (ov == cv && oi < ci)) { cv = ov; ci = oi; }
            }
            if (lane == 0) {
                g_t5v[row * 640 + sl * 5 + j] = cv;
                g_t5i[row * 640 + sl * 5 + j] = ci;
            }
            if (col == ci) chosen = true;
        }
        if (lane == 0) { g_rmax[row * 128 + sl] = mx; g_rsum[row * 128 + sl] = se; }
    }
}

// topk merge + state update: 8 CTAs (one per batch).
__device__ void topk_stage(int b, int cur) {
    int tid = threadIdx.x;
    int nxt = cur ^ 1;
    int warp = tid >> 5, lane = tid & 31;
    unsigned full = 0xffffffffu;
    __shared__ float t_rv[25];
    __shared__ int   t_ri[25];
    __shared__ float t_fv[KBM];
    __shared__ int   t_fi[KBM];
    __shared__ int   t_par[KBM], t_tok[KBM], t_blk2[KBM], t_plen[KBM];

    if (warp < KBM) {
        int row = b * KBM + warp;
        float rm[4], rs[4];
#pragma unroll
        for (int q = 0; q < 4; q++) {
            rm[q] = g_rmax[row * 128 + lane * 4 + q];
            rs[q] = g_rsum[row * 128 + lane * 4 + q];
        }
        float M = fmaxf(fmaxf(rm[0], rm[1]), fmaxf(rm[2], rm[3]));
#pragma unroll
        for (int off = 16; off > 0; off >>= 1)
            M = fmaxf(M, __shfl_xor_sync(full, M, off));
        float S = 0.f;
#pragma unroll
        for (int q = 0; q < 4; q++) S += rs[q] * expf(rm[q] - M);
#pragma unroll
        for (int off = 16; off > 0; off >>= 1)
            S += __shfl_xor_sync(full, S, off);
        float lse = M + logf(S);
        float sc = g_scores[cur][row];
        int selg[KBM]; float selv[KBM];
        for (int j = 0; j < KBM; j++) {
            float bv = NEGF; int bi = 0x7fffffff;
            for (int q = 0; q < 20; q++) {
                int c = lane * 20 + q;
                int gidx = warp * 4096 + g_t5i[row * 640 + c];
                bool skip = false;
                for (int p = 0; p < j; p++) if (gidx == selg[p]) skip = true;
                if (skip) continue;
                float adj = sc + g_t5v[row * 640 + c] - lse;
                if (adj > bv || (adj == bv && gidx < bi)) { bv = adj; bi = gidx; }
            }
#pragma unroll
            for (int off = 16; off > 0; off >>= 1) {
                float ov = __shfl_xor_sync(full, bv, off);
                int   oi = __shfl_xor_sync(full, bi, off);
                if (ov > bv || (ov == bv && oi < bi)) { bv = ov; bi = oi; }
            }
            selg[j] = bi; selv[j] = bv;
        }
        if (lane == 0) {
#pragma unroll
            for (int j = 0; j < KBM; j++) {
                t_rv[warp * KBM + j] = selv[j];
                t_ri[warp * KBM + j] = selg[j];
            }
        }
    }
    __syncthreads();
    if (warp == 0) {
        float v  = (lane < 25) ? t_rv[lane] : NEGF;
        int   gi = (lane < 25) ? t_ri[lane] : 0x7fffffff;
        bool chosen = false;
        for (int j = 0; j < KBM; j++) {
            float cv = chosen ? NEGF : v;
            int ci = gi;
#pragma unroll
            for (int off = 16; off > 0; off >>= 1) {
                float ov = __shfl_xor_sync(full, cv, off);
                int   oi = __shfl_xor_sync(full, ci, off);
                if (ov > cv || (ov == cv && oi < ci)) { cv = ov; ci = oi; }
            }
            if (lane == 0) { t_fv[j] = cv; t_fi[j] = ci; }
            if (gi == ci) chosen = true;
        }
    }
    __syncthreads();
    if (tid < KBM) {
        int idx = t_fi[tid];
        int par = idx >> 12, tok = idx & 4095;
        int blank = (tok == 0);
        int p = b * KBM + par, mn = b * KBM + tid;
        t_par[tid] = par; t_tok[tid] = tok; t_blk2[tid] = blank;
        int pl = g_lens[cur][p];
        t_plen[tid] = pl;
        g_scores[nxt][mn] = t_fv[tid];
        g_lens[nxt][mn]   = pl + (blank ? 0 : 1);
        g_tokens[nxt][mn] = blank ? g_tokens[cur][p] : tok;
    }
    __syncthreads();
    for (int j = 0; j < KBM; j++) {
        int p = b * KBM + t_par[j], mn = b * KBM + j;
        bool blank = (t_blk2[j] != 0);
        const float* hs = blank ? &g_h[cur][p * HH] : &g_hnew[p * HH];
        const float* cs = blank ? &g_c[cur][p * HH] : &g_cnew[p * HH];
        for (int i = tid; i < HH; i += 256) {
            g_h[nxt][mn * HH + i] = hs[i];
            g_c[nxt][mn * HH + i] = cs[i];
        }
        for (int i = tid; i < TT; i += 256) {
            int v = g_preds[cur][p * TT + i];
            if (!blank && i == t_plen[j]) v = t_tok[j];
            g_preds[nxt][mn * TT + i] = v;
        }
    }
}

// ----------------------------- finalize -------------------------------------
__device__ void finalize_stage(float* __restrict__ out) {
    int tid = threadIdx.x;
    __shared__ float s_norm[MM];
    __shared__ int   s_best[BB];
    if (tid < MM)
        s_norm[tid] = g_scores[0][tid] / ((float)g_lens[0][tid] + 1.0f);
    __syncthreads();
    if (tid < BB) {
        float bv = NEGF; int bj = 0;
        for (int j = 0; j < KBM; j++) {
            float v = s_norm[tid * KBM + j];
            if (v > bv) { bv = v; bj = j; }
        }
        s_best[tid] = bj;
        out[BB * TT + tid] = (float)g_lens[0][tid * KBM + bj];
    }
    if (tid < MM) out[BB * TT + BB + 1 + tid] = s_norm[tid];
    __syncthreads();
    if (tid == 0) {
        float acc = 0.0f;
        for (int b2 = 0; b2 < BB; b2++) {
            float bv = NEGF;
            for (int j = 0; j < KBM; j++) bv = fmaxf(bv, s_norm[b2 * KBM + j]);
            acc += expf(bv);
        }
        out[BB * TT + BB] = acc / (float)BB;
    }
    for (int b2 = 0; b2 < BB; b2++) {
        int m = b2 * KBM + s_best[b2];
        for (int i = tid; i < TT; i += 256)
            out[b2 * TT + i] = (float)g_preds[0][m * TT + i];
    }
}

// ----------------------------- persistent kernel ----------------------------
__global__ __launch_bounds__(256, 3) void persist(const float* __restrict__ E,
                                                  const float* __restrict__ Wpn,
                                                  const float* __restrict__ b_joint,
                                                  const float* __restrict__ Wout,
                                                  const float* __restrict__ bout,
                                                  float* __restrict__ out) {
    __shared__ Smem sm;
    unsigned int ph = 0;
    int blk = blockIdx.x;
    for (int t = 0; t < TT; t++) {
        int cur = t & 1;
        if (blk < 416) gates_stage(&sm, blk, cur, E);
        gbar(ph);
        if (blk < 256) pn_stage(&sm, blk, cur, Wpn);
        gbar(ph);
        joint_stage(b_joint, t, blk);
        gbar(ph);
        if (blk < 416) out_stage(&sm, blk, Wout);
        gbar(ph);
        stats_stage(blk, bout);
        gbar(ph);
        if (blk < BB) topk_stage(blk, cur);
        gbar(ph);
    }
    if (blk == 0) finalize_stage(out);
}

// ----------------------------- launch ---------------------------------------
extern "C" void kernel_launch(void* const* d_in, const int* in_sizes, int n_in,
                              void* d_out, int out_size) {
    const float* tn      = (const float*)d_in[0];
    const float* E       = (const float*)d_in[1];
    const float* W_ih    = (const float*)d_in[2];
    const float* W_hh    = (const float*)d_in[3];
    const float* b_lstm  = (const float*)d_in[4];
    const float* W_tn    = (const float*)d_in[5];
    const float* W_pn    = (const float*)d_in[6];
    const float* b_joint = (const float*)d_in[7];
    const float* W_out   = (const float*)d_in[8];
    const float* b_out   = (const float*)d_in[9];
    float* out = (float*)d_out;

    init_state<<<160, 256>>>(b_lstm);
    permute_w<<<dim3(64, 128), dim3(32, 8)>>>(W_ih, W_hh);
    tnproj_gemm<<<dim3(16, 16), 256>>>(tn, W_tn);
    persist<<<GRID_ALL, 256>>>(E, W_pn, b_joint, W_out, b_out, out);
}